// round 15
// baseline (speedup 1.0000x reference)
#include <cuda_runtime.h>
#include <cuda_fp16.h>
#include <math.h>
#include <stdint.h>

// NT-Xent R15: R13 config (2 CTAs/SM x 256 thr, warp tile 32x64, bulk loader)
// + double-buffered accumulators with the exp epilogue of tile t-1 interleaved
// into tile t's K-loop (fills LDSM/MMA dependency stalls with MUFU/FMA work).

#define TWO_N   8192
#define N_HALF  4096
#define CDIM    128
#define NBLK    64
#define TILES   2080                         // 64*65/2
#define GRID    296                          // 2 CTAs per SM
#define INV_T   14.285714285714286f
#define K1      20.60984248218323f           // INV_T * log2(e)
#define BLKB    32768                        // one 128-row fp16 block

#define OFF_A   0
#define OFF_B0  BLKB
#define OFF_B1  (2 * BLKB)
#define OFF_RED (3 * BLKB)                   // 98304
#define SMEM_DYN (OFF_RED + 128 * 3 * 4 + 128 * 5 * 4)   // 102400

__device__ __align__(128) __half g_Fs[TWO_N * CDIM];   // swizzled 128-row blocks
__device__ float g_part[NBLK * NBLK * 128];
__device__ float g_pos[TWO_N];
__device__ double g_bsum[32];
__device__ int g_ctr;
__device__ int g_sense;
__device__ int g_count;

__device__ __forceinline__ uint32_t smem_u32(const void* p) {
    uint32_t a;
    asm("{ .reg .u64 t; cvta.to.shared.u64 t, %1; cvt.u32.u64 %0, t; }"
        : "=r"(a) : "l"(p));
    return a;
}
__device__ __forceinline__ float ex2f(float x) {
    float r;
    asm("ex2.approx.ftz.f32 %0, %1;" : "=f"(r) : "f"(x));
    return r;
}
__device__ __forceinline__ void bulk_cp(uint32_t s, const void* g,
                                        uint32_t bytes, uint32_t mbar) {
    asm volatile(
        "cp.async.bulk.shared::cta.global.mbarrier::complete_tx::bytes "
        "[%0], [%1], %2, [%3];"
        :: "r"(s), "l"(g), "r"(bytes), "r"(mbar) : "memory");
}
#define MBAR_INIT(a, n) \
    asm volatile("mbarrier.init.shared.b64 [%0], %1;" :: "r"(a), "r"(n) : "memory")
#define MBAR_EXPECT(a, bytes) \
    asm volatile("mbarrier.arrive.expect_tx.shared.b64 _, [%0], %1;" \
                 :: "r"(a), "r"((uint32_t)(bytes)) : "memory")
#define MBAR_WAIT(a, ph) do {                                                  \
    uint32_t _m = (a), _p = (ph), _d;                                          \
    asm volatile("{\n\t.reg .pred p;\n\t"                                      \
        "mbarrier.try_wait.parity.acquire.cta.shared::cta.b64 p, [%1], %2;\n\t"\
        "selp.b32 %0, 1, 0, p;\n\t}"                                           \
        : "=r"(_d) : "r"(_m), "r"(_p) : "memory");                             \
    if (!_d) {                                                                 \
        asm volatile("{\n\t.reg .pred P1;\n\t"                                 \
            "W%=:\n\t"                                                         \
            "mbarrier.try_wait.parity.acquire.cta.shared::cta.b64 P1, [%0], %1, 0x989680;\n\t" \
            "@P1 bra.uni D%=;\n\t"                                             \
            "bra.uni W%=;\n\t"                                                 \
            "D%=:\n\t}" :: "r"(_m), "r"(_p) : "memory");                       \
    } } while (0)
#define FENCE_PROXY() asm volatile("fence.proxy.async;" ::: "memory")

#define LDSM_X4(r0, r1, r2, r3, addr)                                          \
    asm volatile("ldmatrix.sync.aligned.m8n8.x4.shared.b16 {%0,%1,%2,%3},[%4];"\
        : "=r"(r0), "=r"(r1), "=r"(r2), "=r"(r3) : "r"(addr))

#define MMA16816H(c, a, b0, b1)                                                \
    asm volatile("mma.sync.aligned.m16n8k16.row.col.f16.f16.f16.f16 "          \
        "{%0,%1},{%2,%3,%4,%5},{%6,%7},{%0,%1};"                               \
        : "+r"((c)[0]), "+r"((c)[1])                                           \
        : "r"((a)[0]), "r"((a)[1]), "r"((a)[2]), "r"((a)[3]),                  \
          "r"(b0), "r"(b1))

__device__ __forceinline__ void gbar(int tid, int& target) {
    __syncthreads();
    if (tid == 0) {
        __threadfence();
        if (atomicAdd(&g_count, 1) == GRID - 1) {
            g_count = 0;
            __threadfence();
            atomicAdd(&g_sense, 1);
        } else {
            while (((volatile int*)&g_sense)[0] - target < 0) {}
            __threadfence();
        }
    }
    __syncthreads();
    target++;
}

extern __shared__ char dynsmem[];

__global__ void __launch_bounds__(256, 2) ntxent_fused_kernel(
        const float* __restrict__ f1, const float* __restrict__ f2,
        float* __restrict__ out) {
    const int tid  = threadIdx.x;
    const int lane = tid & 31;
    const int wid  = tid >> 5;       // 0..7
    const int wm   = wid & 3;        // 4 m-warps x 32 rows
    const int wn   = wid >> 2;       // 2 n-warps x 64 cols
    const int bx   = blockIdx.x;

    __shared__ __align__(8) uint64_t s_mbar[2];
    __shared__ int sTgt;
    const uint32_t mb[2] = { smem_u32(&s_mbar[0]), smem_u32(&s_mbar[1]) };

    if (tid == 0) {
        sTgt = ((volatile int*)&g_sense)[0] + 1;
        MBAR_INIT(mb[0], 1);
        MBAR_INIT(mb[1], 1);
        FENCE_PROXY();
    }
    __syncthreads();
    int target = sTgt;

    // ---------------- Phase A: normalize + swizzled fp16 + pos ----------------
    for (int i = bx * 8 + wid; i < N_HALF; i += GRID * 8) {
        float4 a = *(const float4*)(f1 + (size_t)i * CDIM + lane * 4);
        float4 b = *(const float4*)(f2 + (size_t)i * CDIM + lane * 4);
        float s1 = a.x * a.x + a.y * a.y + a.z * a.z + a.w * a.w;
        float s2 = b.x * b.x + b.y * b.y + b.z * b.z + b.w * b.w;
        float d  = a.x * b.x + a.y * b.y + a.z * b.z + a.w * b.w;
        #pragma unroll
        for (int o = 16; o; o >>= 1) {
            s1 += __shfl_xor_sync(0xffffffffu, s1, o);
            s2 += __shfl_xor_sync(0xffffffffu, s2, o);
            d  += __shfl_xor_sync(0xffffffffu, d,  o);
        }
        float i1 = 1.0f / fmaxf(sqrtf(s1), 1e-12f);
        float i2 = 1.0f / fmaxf(sqrtf(s2), 1e-12f);

        int c16 = lane >> 1, hf = lane & 1;
        {
            int r = i & 127;
            uint32_t off = (uint32_t)(i >> 7) * BLKB + (uint32_t)r * 256
                         + (uint32_t)((c16 ^ (r & 7)) * 16) + (uint32_t)hf * 8;
            __half2 h0 = __floats2half2_rn(a.x * i1, a.y * i1);
            __half2 h1 = __floats2half2_rn(a.z * i1, a.w * i1);
            uint2 u; u.x = *(uint32_t*)&h0; u.y = *(uint32_t*)&h1;
            *(uint2*)((char*)g_Fs + off) = u;
        }
        {
            int j = i + N_HALF;
            int r = j & 127;
            uint32_t off = (uint32_t)(j >> 7) * BLKB + (uint32_t)r * 256
                         + (uint32_t)((c16 ^ (r & 7)) * 16) + (uint32_t)hf * 8;
            __half2 g0 = __floats2half2_rn(b.x * i2, b.y * i2);
            __half2 g1 = __floats2half2_rn(b.z * i2, b.w * i2);
            uint2 u; u.x = *(uint32_t*)&g0; u.y = *(uint32_t*)&g1;
            *(uint2*)((char*)g_Fs + off) = u;
        }
        if (lane == 0) {
            float pos = (d * i1 * i2 - 1.0f) * INV_T;
            g_pos[i] = pos;
            g_pos[i + N_HALF] = pos;
        }
    }

    gbar(tid, target);
    FENCE_PROXY();

    // ---------------- Phase B: HMMA 128x128 tiles, interleaved epilogue -------
    {
        uint32_t sb = smem_u32(dynsmem);
        const uint32_t bufA    = sb + OFF_A;
        const uint32_t bufB[2] = { sb + OFF_B0, sb + OFF_B1 };
        float* sRow = (float*)(dynsmem + OFF_RED);   // [128][3]
        float* sCol = sRow + 128 * 3;                // [128][5]

        const int rowA  = wm * 32 + (lane & 15);
        const int r7A   = rowA & 7;
        const int cbA   = lane >> 4;
        const uint32_t aRB = (uint32_t)rowA * 256;
        const int rlowB = (lane & 7) + ((lane >> 4) & 1) * 8;
        const int cbB   = (lane >> 3) & 1;

        uint32_t accA[2][8][2], accB[2][8][2];
        float pr[4], pc[16];
        #pragma unroll
        for (int h = 0; h < 4; h++) pr[h] = 0.f;
        #pragma unroll
        for (int h = 0; h < 16; h++) pc[h] = 0.f;

        // One packed acc reg: 2 adjacent cols of row-group rg.
        auto epi_reg = [&](uint32_t v, int e) {
            const int mi = e >> 4, ni = (e >> 1) & 7, rg = e & 1;
            float2 f = __half22float2(*(const __half2*)&v);
            float e0 = ex2f(fmaf(f.x, K1, -K1));
            float e1 = ex2f(fmaf(f.y, K1, -K1));
            pr[mi * 2 + rg] += e0 + e1;
            pc[ni * 2]     += e0;
            pc[ni * 2 + 1] += e1;
        };

        // K-loop into accC; optionally interleave epilogue of accP (4 regs/ks).
        auto kloop = [&](uint32_t (&accC)[2][8][2], uint32_t (&accP)[2][8][2],
                         uint32_t bBuf, int doEpi) {
            #pragma unroll
            for (int mi = 0; mi < 2; mi++)
                #pragma unroll
                for (int ni = 0; ni < 8; ni++) {
                    accC[mi][ni][0] = 0u; accC[mi][ni][1] = 0u;
                }
            #pragma unroll
            for (int ks = 0; ks < 8; ks++) {
                uint32_t afr[2][4], bfr[4][4];
                const uint32_t aoff = (uint32_t)(((ks * 2 + cbA) ^ r7A) * 16);
                #pragma unroll
                for (int mi = 0; mi < 2; mi++) {
                    uint32_t ad = bufA + aRB + (uint32_t)(mi * 16 * 256) + aoff;
                    LDSM_X4(afr[mi][0], afr[mi][1], afr[mi][2], afr[mi][3], ad);
                }
                #pragma unroll
                for (int np = 0; np < 4; np++) {
                    int rB  = wn * 64 + np * 16 + rlowB;
                    uint32_t boff = (uint32_t)(((ks * 2 + cbB) ^ (rB & 7)) * 16);
                    uint32_t bd = bBuf + (uint32_t)rB * 256 + boff;
                    LDSM_X4(bfr[np][0], bfr[np][1], bfr[np][2], bfr[np][3], bd);
                }
                #pragma unroll
                for (int mi = 0; mi < 2; mi++)
                    #pragma unroll
                    for (int ni = 0; ni < 8; ni++)
                        MMA16816H(accC[mi][ni], afr[mi],
                                  bfr[ni >> 1][(ni & 1) * 2],
                                  bfr[ni >> 1][(ni & 1) * 2 + 1]);
                if (doEpi) {
                    #pragma unroll
                    for (int j = 0; j < 4; j++) {
                        const int e = ks * 4 + j;
                        epi_reg(accP[e >> 4][(e >> 1) & 7][e & 1], e);
                    }
                }
            }
        };

        auto epi_all = [&](uint32_t (&acc)[2][8][2]) {
            #pragma unroll
            for (int e = 0; e < 32; e++)
                epi_reg(acc[e >> 4][(e >> 1) & 7][e & 1], e);
        };

        // Diag fixup + reductions + writeout for finished tile (pI,pJ).
        auto finish = [&](uint32_t (&acc)[2][8][2], int pI, int pJ) {
            if (pI == pJ) {
                #pragma unroll
                for (int mi = 0; mi < 2; mi++)
                    #pragma unroll
                    for (int ni = 0; ni < 8; ni++)
                        #pragma unroll
                        for (int rg = 0; rg < 2; rg++) {
                            int rT = wm * 32 + mi * 16 + (lane >> 2) + 8 * rg;
                            int cB = wn * 64 + ni * 8 + (lane & 3) * 2;
                            if (cB == rT || cB + 1 == rT) {
                                float2 f = __half22float2(
                                    *(const __half2*)&acc[mi][ni][rg]);
                                float fd = (cB == rT) ? f.x : f.y;
                                pr[mi * 2 + rg] -= ex2f(fmaf(fd, K1, -K1));
                            }
                        }
            }
            #pragma unroll
            for (int h = 0; h < 4; h++) {
                pr[h] += __shfl_xor_sync(0xffffffffu, pr[h], 1);
                pr[h] += __shfl_xor_sync(0xffffffffu, pr[h], 2);
            }
            #pragma unroll
            for (int h = 0; h < 16; h++) {
                pc[h] += __shfl_xor_sync(0xffffffffu, pc[h], 4);
                pc[h] += __shfl_xor_sync(0xffffffffu, pc[h], 8);
                pc[h] += __shfl_xor_sync(0xffffffffu, pc[h], 16);
            }
            if ((lane & 3) == 0) {
                #pragma unroll
                for (int h = 0; h < 4; h++) {
                    int r = wm * 32 + (h >> 1) * 16 + (lane >> 2) + 8 * (h & 1);
                    sRow[r * 3 + wn] = pr[h];
                }
            }
            if (lane < 4) {
                #pragma unroll
                for (int h = 0; h < 16; h++) {
                    int c = wn * 64 + (h >> 1) * 8 + lane * 2 + (h & 1);
                    sCol[c * 5 + wm] = pc[h];
                }
            }
            __syncthreads();
            if (tid < 128) {
                g_part[((size_t)pI * NBLK + pJ) * 128 + tid] =
                    sRow[tid * 3] + sRow[tid * 3 + 1];
            } else {
                int c = tid - 128;
                if (pJ > pI)
                    g_part[((size_t)pJ * NBLK + pI) * 128 + c] =
                        sCol[c * 5] + sCol[c * 5 + 1]
                      + sCol[c * 5 + 2] + sCol[c * 5 + 3];
            }
            __syncthreads();
            #pragma unroll
            for (int h = 0; h < 4; h++) pr[h] = 0.f;
            #pragma unroll
            for (int h = 0; h < 16; h++) pc[h] = 0.f;
        };

        // Contiguous range of 128x128 tiles.
        const int s = (int)(((long long)bx * TILES) / GRID);
        const int e = (int)(((long long)(bx + 1) * TILES) / GRID);
        int I = 0, rem = s;
        while (rem >= NBLK - I) { rem -= NBLK - I; I++; }
        int J = I + rem;
        const int nt = e - s;

        int ph[2] = { 0, 0 };
        if (tid == 0) {
            MBAR_EXPECT(mb[0], 2 * BLKB);
            bulk_cp(bufA, (const char*)g_Fs + (size_t)I * BLKB, BLKB, mb[0]);
            bulk_cp(bufB[0], (const char*)g_Fs + (size_t)J * BLKB, BLKB, mb[0]);
        }

        int cI = I, cJ = J, prevI = 0, prevJ = 0;
        for (int t = 0; t < nt; t++) {
            const int cur = t & 1;
            MBAR_WAIT(mb[cur], ph[cur]); ph[cur] ^= 1;

            const bool haveNext = (t + 1 < nt);
            int pI = cI, pJ = cJ + 1;
            if (pJ == NBLK) { pI = cI + 1; pJ = pI; }
            const bool newA = haveNext && (pI != cI);

            if (tid == 0 && haveNext) {
                MBAR_EXPECT(mb[cur ^ 1], newA ? 2 * BLKB : BLKB);
                bulk_cp(bufB[cur ^ 1], (const char*)g_Fs + (size_t)pJ * BLKB,
                        BLKB, mb[cur ^ 1]);
            }

            if (cur) kloop(accB, accA, bufB[cur], t > 0);
            else     kloop(accA, accB, bufB[cur], t > 0);

            if (t > 0) {
                if (cur) finish(accA, prevI, prevJ);
                else     finish(accB, prevI, prevJ);
            } else {
                __syncthreads();   // all warps done with bufA/bufB[0] reads
            }

            if (tid == 0 && newA) {
                FENCE_PROXY();     // order prior generic A-reads before overwrite
                bulk_cp(bufA, (const char*)g_Fs + (size_t)pI * BLKB,
                        BLKB, mb[cur ^ 1]);
            }
            prevI = cI; prevJ = cJ;
            cI = pI; cJ = pJ;
        }
        // Flush final tile.
        if ((nt - 1) & 1) { epi_all(accB); finish(accB, prevI, prevJ); }
        else              { epi_all(accA); finish(accA, prevI, prevJ); }
    }

    gbar(tid, target);

    // ---------------- Phase C: gather + deterministic final sum ----------------
    if (bx < 32) {
        double* sm = (double*)dynsmem;
        int row = bx * 256 + tid;
        int R = row >> 7, m = row & 127;
        float s = 0.f;
        #pragma unroll 8
        for (int O = 0; O < NBLK; O++)
            s += g_part[((size_t)R * NBLK + O) * 128 + m];
        sm[tid] = (double)(g_pos[row] - logf(s));
        __syncthreads();
        #pragma unroll
        for (int o = 128; o; o >>= 1) {
            if (tid < o) sm[tid] += sm[tid + o];
            __syncthreads();
        }
        __shared__ int isLast;
        if (tid == 0) {
            g_bsum[bx] = sm[0];
            __threadfence();
            isLast = (atomicAdd(&g_ctr, 1) == 31);
        }
        __syncthreads();
        if (isLast && tid == 0) {
            double tot = 0.0;
            #pragma unroll
            for (int i = 0; i < 32; i++) tot += g_bsum[i];
            out[0] = (float)(-tot / (double)TWO_N);
            g_ctr = 0;   // reset for graph replay
        }
    }
}

// ---------------------------------------------------------------------------
extern "C" void kernel_launch(void* const* d_in, const int* in_sizes, int n_in,
                              void* d_out, int out_size) {
    const float* f1 = (const float*)d_in[0];
    const float* f2 = (const float*)d_in[1];
    float* out = (float*)d_out;

    cudaFuncSetAttribute(ntxent_fused_kernel,
                         cudaFuncAttributeMaxDynamicSharedMemorySize, SMEM_DYN);

    ntxent_fused_kernel<<<GRID, 256, SMEM_DYN>>>(f1, f2, out);
}

// round 16
// speedup vs baseline: 1.1441x; 1.1441x over previous
#include <cuda_runtime.h>
#include <cuda_fp16.h>
#include <math.h>
#include <stdint.h>

// NT-Xent R16: R13 config (2 CTAs/SM x 256 thr, warp tile 32x64, bulk loader)
// with fp16x2 SIMD epilogue: ex2.approx.f16x2 (2 exps/MUFU op), HFMA2/HADD2
// accumulation, +13 exponent bias to keep scaled exps fp16-normal (phase C
// subtracts 13*ln2). Diagonal handled by masking before accumulation.

#define TWO_N   8192
#define N_HALF  4096
#define CDIM    128
#define NBLK    64
#define TILES   2080                         // 64*65/2
#define GRID    296                          // 2 CTAs per SM
#define INV_T   14.285714285714286f
#define K1F     20.60984248218323f           // INV_T * log2(e)
#define C13F    (-20.60984248218323f + 13.0f)
#define LN2x13  9.010913347279288f
#define BLKB    32768                        // one 128-row fp16 block

#define OFF_A   0
#define OFF_B0  BLKB
#define OFF_B1  (2 * BLKB)
#define OFF_RED (3 * BLKB)                   // 98304
#define SMEM_DYN (OFF_RED + 128 * 3 * 4 + 128 * 5 * 4)   // 102400

__device__ __align__(128) __half g_Fs[TWO_N * CDIM];   // swizzled 128-row blocks
__device__ float g_part[NBLK * NBLK * 128];
__device__ float g_pos[TWO_N];
__device__ double g_bsum[32];
__device__ int g_ctr;
__device__ int g_sense;
__device__ int g_count;

__device__ __forceinline__ uint32_t smem_u32(const void* p) {
    uint32_t a;
    asm("{ .reg .u64 t; cvta.to.shared.u64 t, %1; cvt.u32.u64 %0, t; }"
        : "=r"(a) : "l"(p));
    return a;
}
__device__ __forceinline__ uint32_t ex2_h2(uint32_t x) {
    uint32_t r;
    asm("ex2.approx.f16x2 %0, %1;" : "=r"(r) : "r"(x));
    return r;
}
__device__ __forceinline__ void bulk_cp(uint32_t s, const void* g,
                                        uint32_t bytes, uint32_t mbar) {
    asm volatile(
        "cp.async.bulk.shared::cta.global.mbarrier::complete_tx::bytes "
        "[%0], [%1], %2, [%3];"
        :: "r"(s), "l"(g), "r"(bytes), "r"(mbar) : "memory");
}
#define MBAR_INIT(a, n) \
    asm volatile("mbarrier.init.shared.b64 [%0], %1;" :: "r"(a), "r"(n) : "memory")
#define MBAR_EXPECT(a, bytes) \
    asm volatile("mbarrier.arrive.expect_tx.shared.b64 _, [%0], %1;" \
                 :: "r"(a), "r"((uint32_t)(bytes)) : "memory")
#define MBAR_WAIT(a, ph) do {                                                  \
    uint32_t _m = (a), _p = (ph), _d;                                          \
    asm volatile("{\n\t.reg .pred p;\n\t"                                      \
        "mbarrier.try_wait.parity.acquire.cta.shared::cta.b64 p, [%1], %2;\n\t"\
        "selp.b32 %0, 1, 0, p;\n\t}"                                           \
        : "=r"(_d) : "r"(_m), "r"(_p) : "memory");                             \
    if (!_d) {                                                                 \
        asm volatile("{\n\t.reg .pred P1;\n\t"                                 \
            "W%=:\n\t"                                                         \
            "mbarrier.try_wait.parity.acquire.cta.shared::cta.b64 P1, [%0], %1, 0x989680;\n\t" \
            "@P1 bra.uni D%=;\n\t"                                             \
            "bra.uni W%=;\n\t"                                                 \
            "D%=:\n\t}" :: "r"(_m), "r"(_p) : "memory");                       \
    } } while (0)
#define FENCE_PROXY() asm volatile("fence.proxy.async;" ::: "memory")

#define LDSM_X4(r0, r1, r2, r3, addr)                                          \
    asm volatile("ldmatrix.sync.aligned.m8n8.x4.shared.b16 {%0,%1,%2,%3},[%4];"\
        : "=r"(r0), "=r"(r1), "=r"(r2), "=r"(r3) : "r"(addr))

#define MMA16816H(c, a, b0, b1)                                                \
    asm volatile("mma.sync.aligned.m16n8k16.row.col.f16.f16.f16.f16 "          \
        "{%0,%1},{%2,%3,%4,%5},{%6,%7},{%0,%1};"                               \
        : "+r"((c)[0]), "+r"((c)[1])                                           \
        : "r"((a)[0]), "r"((a)[1]), "r"((a)[2]), "r"((a)[3]),                  \
          "r"(b0), "r"(b1))

__device__ __forceinline__ void gbar(int tid, int& target) {
    __syncthreads();
    if (tid == 0) {
        __threadfence();
        if (atomicAdd(&g_count, 1) == GRID - 1) {
            g_count = 0;
            __threadfence();
            atomicAdd(&g_sense, 1);
        } else {
            while (((volatile int*)&g_sense)[0] - target < 0) {}
            __threadfence();
        }
    }
    __syncthreads();
    target++;
}

extern __shared__ char dynsmem[];

__global__ void __launch_bounds__(256, 2) ntxent_fused_kernel(
        const float* __restrict__ f1, const float* __restrict__ f2,
        float* __restrict__ out) {
    const int tid  = threadIdx.x;
    const int lane = tid & 31;
    const int wid  = tid >> 5;       // 0..7
    const int wm   = wid & 3;        // 4 m-warps x 32 rows
    const int wn   = wid >> 2;       // 2 n-warps x 64 cols
    const int bx   = blockIdx.x;

    __shared__ __align__(8) uint64_t s_mbar[2];
    __shared__ int sTgt;
    const uint32_t mb[2] = { smem_u32(&s_mbar[0]), smem_u32(&s_mbar[1]) };

    if (tid == 0) {
        sTgt = ((volatile int*)&g_sense)[0] + 1;
        MBAR_INIT(mb[0], 1);
        MBAR_INIT(mb[1], 1);
        FENCE_PROXY();
    }
    __syncthreads();
    int target = sTgt;

    // ---------------- Phase A: normalize + swizzled fp16 + pos ----------------
    for (int i = bx * 8 + wid; i < N_HALF; i += GRID * 8) {
        float4 a = *(const float4*)(f1 + (size_t)i * CDIM + lane * 4);
        float4 b = *(const float4*)(f2 + (size_t)i * CDIM + lane * 4);
        float s1 = a.x * a.x + a.y * a.y + a.z * a.z + a.w * a.w;
        float s2 = b.x * b.x + b.y * b.y + b.z * b.z + b.w * b.w;
        float d  = a.x * b.x + a.y * b.y + a.z * b.z + a.w * b.w;
        #pragma unroll
        for (int o = 16; o; o >>= 1) {
            s1 += __shfl_xor_sync(0xffffffffu, s1, o);
            s2 += __shfl_xor_sync(0xffffffffu, s2, o);
            d  += __shfl_xor_sync(0xffffffffu, d,  o);
        }
        float i1 = 1.0f / fmaxf(sqrtf(s1), 1e-12f);
        float i2 = 1.0f / fmaxf(sqrtf(s2), 1e-12f);

        int c16 = lane >> 1, hf = lane & 1;
        {
            int r = i & 127;
            uint32_t off = (uint32_t)(i >> 7) * BLKB + (uint32_t)r * 256
                         + (uint32_t)((c16 ^ (r & 7)) * 16) + (uint32_t)hf * 8;
            __half2 h0 = __floats2half2_rn(a.x * i1, a.y * i1);
            __half2 h1 = __floats2half2_rn(a.z * i1, a.w * i1);
            uint2 u; u.x = *(uint32_t*)&h0; u.y = *(uint32_t*)&h1;
            *(uint2*)((char*)g_Fs + off) = u;
        }
        {
            int j = i + N_HALF;
            int r = j & 127;
            uint32_t off = (uint32_t)(j >> 7) * BLKB + (uint32_t)r * 256
                         + (uint32_t)((c16 ^ (r & 7)) * 16) + (uint32_t)hf * 8;
            __half2 g0 = __floats2half2_rn(b.x * i2, b.y * i2);
            __half2 g1 = __floats2half2_rn(b.z * i2, b.w * i2);
            uint2 u; u.x = *(uint32_t*)&g0; u.y = *(uint32_t*)&g1;
            *(uint2*)((char*)g_Fs + off) = u;
        }
        if (lane == 0) {
            float pos = (d * i1 * i2 - 1.0f) * INV_T;
            g_pos[i] = pos;
            g_pos[i + N_HALF] = pos;
        }
    }

    gbar(tid, target);
    FENCE_PROXY();

    // ---------------- Phase B: HMMA 128x128 tiles, fp16x2 epilogue ------------
    {
        uint32_t sb = smem_u32(dynsmem);
        const uint32_t bufA    = sb + OFF_A;
        const uint32_t bufB[2] = { sb + OFF_B0, sb + OFF_B1 };
        float* sRow = (float*)(dynsmem + OFF_RED);   // [128][3]
        float* sCol = sRow + 128 * 3;                // [128][5]

        const int rowA  = wm * 32 + (lane & 15);
        const int r7A   = rowA & 7;
        const int cbA   = lane >> 4;
        const uint32_t aRB = (uint32_t)rowA * 256;
        const int rlowB = (lane & 7) + ((lane >> 4) & 1) * 8;
        const int cbB   = (lane >> 3) & 1;

        const __half2 K1h = __float2half2_rn(K1F);
        const __half2 Ch  = __float2half2_rn(C13F);

        auto compute_tile = [&](uint32_t bBuf, int I, int J) {
            uint32_t acc[2][8][2];
            #pragma unroll
            for (int mi = 0; mi < 2; mi++)
                #pragma unroll
                for (int ni = 0; ni < 8; ni++) {
                    acc[mi][ni][0] = 0u; acc[mi][ni][1] = 0u;
                }
            #pragma unroll
            for (int ks = 0; ks < 8; ks++) {
                uint32_t afr[2][4], bfr[4][4];
                const uint32_t aoff = (uint32_t)(((ks * 2 + cbA) ^ r7A) * 16);
                #pragma unroll
                for (int mi = 0; mi < 2; mi++) {
                    uint32_t ad = bufA + aRB + (uint32_t)(mi * 16 * 256) + aoff;
                    LDSM_X4(afr[mi][0], afr[mi][1], afr[mi][2], afr[mi][3], ad);
                }
                #pragma unroll
                for (int np = 0; np < 4; np++) {
                    int rB  = wn * 64 + np * 16 + rlowB;
                    uint32_t boff = (uint32_t)(((ks * 2 + cbB) ^ (rB & 7)) * 16);
                    uint32_t bd = bBuf + (uint32_t)rB * 256 + boff;
                    LDSM_X4(bfr[np][0], bfr[np][1], bfr[np][2], bfr[np][3], bd);
                }
                #pragma unroll
                for (int mi = 0; mi < 2; mi++)
                    #pragma unroll
                    for (int ni = 0; ni < 8; ni++)
                        MMA16816H(acc[mi][ni], afr[mi],
                                  bfr[ni >> 1][(ni & 1) * 2],
                                  bfr[ni >> 1][(ni & 1) * 2 + 1]);
            }

            // fp16x2 epilogue: e = 2^(s*K1 - K1 + 13), per-bucket half2 sums.
            __half2 prh[4], pch[8];
            const __half2 hz = __float2half2_rn(0.f);
            #pragma unroll
            for (int h = 0; h < 4; h++) prh[h] = hz;
            #pragma unroll
            for (int h = 0; h < 8; h++) pch[h] = hz;

            if (I != J) {
                #pragma unroll
                for (int mi = 0; mi < 2; mi++)
                    #pragma unroll
                    for (int ni = 0; ni < 8; ni++)
                        #pragma unroll
                        for (int rg = 0; rg < 2; rg++) {
                            __half2 v = *(const __half2*)&acc[mi][ni][rg];
                            __half2 x = __hfma2(v, K1h, Ch);
                            uint32_t eb = ex2_h2(*(uint32_t*)&x);
                            __half2 e = *(__half2*)&eb;
                            prh[mi * 2 + rg] = __hadd2(prh[mi * 2 + rg], e);
                            pch[ni] = __hadd2(pch[ni], e);
                        }
            } else {
                #pragma unroll
                for (int mi = 0; mi < 2; mi++)
                    #pragma unroll
                    for (int ni = 0; ni < 8; ni++)
                        #pragma unroll
                        for (int rg = 0; rg < 2; rg++) {
                            __half2 v = *(const __half2*)&acc[mi][ni][rg];
                            __half2 x = __hfma2(v, K1h, Ch);
                            uint32_t eb = ex2_h2(*(uint32_t*)&x);
                            int rT = wm * 32 + mi * 16 + (lane >> 2) + 8 * rg;
                            int cB = wn * 64 + ni * 8 + (lane & 3) * 2;
                            if (cB == rT)     eb &= 0xFFFF0000u;  // zero diag (low)
                            if (cB + 1 == rT) eb &= 0x0000FFFFu;  // zero diag (high)
                            __half2 e = *(__half2*)&eb;
                            prh[mi * 2 + rg] = __hadd2(prh[mi * 2 + rg], e);
                            pch[ni] = __hadd2(pch[ni], e);
                        }
            }

            // half2 warp reductions: rows over lane^1,^2; cols over ^4,^8,^16.
            #pragma unroll
            for (int h = 0; h < 4; h++) {
                uint32_t u = *(uint32_t*)&prh[h], v;
                v = __shfl_xor_sync(0xffffffffu, u, 1);
                prh[h] = __hadd2(prh[h], *(__half2*)&v);
                u = *(uint32_t*)&prh[h];
                v = __shfl_xor_sync(0xffffffffu, u, 2);
                prh[h] = __hadd2(prh[h], *(__half2*)&v);
            }
            #pragma unroll
            for (int h = 0; h < 8; h++) {
                uint32_t u = *(uint32_t*)&pch[h], v;
                v = __shfl_xor_sync(0xffffffffu, u, 4);
                pch[h] = __hadd2(pch[h], *(__half2*)&v);
                u = *(uint32_t*)&pch[h];
                v = __shfl_xor_sync(0xffffffffu, u, 8);
                pch[h] = __hadd2(pch[h], *(__half2*)&v);
                u = *(uint32_t*)&pch[h];
                v = __shfl_xor_sync(0xffffffffu, u, 16);
                pch[h] = __hadd2(pch[h], *(__half2*)&v);
            }
            if ((lane & 3) == 0) {
                #pragma unroll
                for (int h = 0; h < 4; h++) {
                    int r = wm * 32 + (h >> 1) * 16 + (lane >> 2) + 8 * (h & 1);
                    float2 f = __half22float2(prh[h]);
                    sRow[r * 3 + wn] = f.x + f.y;
                }
            }
            if (lane < 4) {
                #pragma unroll
                for (int h = 0; h < 8; h++) {
                    int c = wn * 64 + h * 8 + lane * 2;
                    float2 f = __half22float2(pch[h]);
                    sCol[c * 5 + wm] = f.x;
                    sCol[(c + 1) * 5 + wm] = f.y;
                }
            }
            __syncthreads();

            if (tid < 128) {
                g_part[((size_t)I * NBLK + J) * 128 + tid] =
                    sRow[tid * 3] + sRow[tid * 3 + 1];
            } else {
                int c = tid - 128;
                if (J > I)
                    g_part[((size_t)J * NBLK + I) * 128 + c] =
                        sCol[c * 5] + sCol[c * 5 + 1]
                      + sCol[c * 5 + 2] + sCol[c * 5 + 3];
            }
            __syncthreads();   // writeout + buffer reads complete
        };

        // Contiguous range of 128x128 tiles.
        const int s = (int)(((long long)bx * TILES) / GRID);
        const int e = (int)(((long long)(bx + 1) * TILES) / GRID);
        int I = 0, rem = s;
        while (rem >= NBLK - I) { rem -= NBLK - I; I++; }
        int J = I + rem;
        const int nt = e - s;

        int ph[2] = { 0, 0 };
        if (tid == 0) {
            MBAR_EXPECT(mb[0], 2 * BLKB);
            bulk_cp(bufA, (const char*)g_Fs + (size_t)I * BLKB, BLKB, mb[0]);
            bulk_cp(bufB[0], (const char*)g_Fs + (size_t)J * BLKB, BLKB, mb[0]);
        }

        int cI = I, cJ = J;
        for (int t = 0; t < nt; t++) {
            const int cur = t & 1;
            MBAR_WAIT(mb[cur], ph[cur]); ph[cur] ^= 1;

            const bool haveNext = (t + 1 < nt);
            int pI = cI, pJ = cJ + 1;
            if (pJ == NBLK) { pI = cI + 1; pJ = pI; }
            const bool newA = haveNext && (pI != cI);

            if (tid == 0 && haveNext) {
                MBAR_EXPECT(mb[cur ^ 1], newA ? 2 * BLKB : BLKB);
                bulk_cp(bufB[cur ^ 1], (const char*)g_Fs + (size_t)pJ * BLKB,
                        BLKB, mb[cur ^ 1]);
            }
            compute_tile(bufB[cur], cI, cJ);
            if (tid == 0 && newA) {
                FENCE_PROXY();   // order prior generic A-reads before overwrite
                bulk_cp(bufA, (const char*)g_Fs + (size_t)pI * BLKB,
                        BLKB, mb[cur ^ 1]);
            }
            cI = pI; cJ = pJ;
        }
    }

    gbar(tid, target);

    // ---------------- Phase C: gather + deterministic final sum ----------------
    if (bx < 32) {
        double* sm = (double*)dynsmem;
        int row = bx * 256 + tid;
        int R = row >> 7, m = row & 127;
        float s = 0.f;
        #pragma unroll 8
        for (int O = 0; O < NBLK; O++)
            s += g_part[((size_t)R * NBLK + O) * 128 + m];
        // sums carry the 2^13 exponent bias
        sm[tid] = (double)(g_pos[row] - logf(s) + LN2x13);
        __syncthreads();
        #pragma unroll
        for (int o = 128; o; o >>= 1) {
            if (tid < o) sm[tid] += sm[tid + o];
            __syncthreads();
        }
        __shared__ int isLast;
        if (tid == 0) {
            g_bsum[bx] = sm[0];
            __threadfence();
            isLast = (atomicAdd(&g_ctr, 1) == 31);
        }
        __syncthreads();
        if (isLast && tid == 0) {
            double tot = 0.0;
            #pragma unroll
            for (int i = 0; i < 32; i++) tot += g_bsum[i];
            out[0] = (float)(-tot / (double)TWO_N);
            g_ctr = 0;   // reset for graph replay
        }
    }
}

// ---------------------------------------------------------------------------
extern "C" void kernel_launch(void* const* d_in, const int* in_sizes, int n_in,
                              void* d_out, int out_size) {
    const float* f1 = (const float*)d_in[0];
    const float* f2 = (const float*)d_in[1];
    float* out = (float*)d_out;

    cudaFuncSetAttribute(ntxent_fused_kernel,
                         cudaFuncAttributeMaxDynamicSharedMemorySize, SMEM_DYN);

    ntxent_fused_kernel<<<GRID, 256, SMEM_DYN>>>(f1, f2, out);
}